// round 1
// baseline (speedup 1.0000x reference)
#include <cuda_runtime.h>

// LIF spike recurrence:
//   mem = mem*TAU + x[t]*alpha; spike = (mem - Vth) > 0; mem = (1-spike)*mem
// TAU = 0.5, T = 8 (leading dim). Each thread owns 4 spatial positions
// (float4), keeps mem in registers, loops over T.

#define TAU 0.5f

__global__ void __launch_bounds__(256) lif_spike_kernel(
    const float* __restrict__ x,
    const float* __restrict__ alpha_p,
    const float* __restrict__ vth_p,
    float* __restrict__ out,
    int spatial /* elements per timestep */)
{
    const float alpha = __ldg(alpha_p);
    const float vth   = __ldg(vth_p);

    int i4 = (blockIdx.x * blockDim.x + threadIdx.x) * 4;
    if (i4 >= spatial) return;

    float m0 = 0.f, m1 = 0.f, m2 = 0.f, m3 = 0.f;

    #pragma unroll
    for (int t = 0; t < 8; t++) {
        const float4 xt = *reinterpret_cast<const float4*>(
            x + (size_t)t * (size_t)spatial + i4);

        m0 = m0 * TAU + xt.x * alpha;
        m1 = m1 * TAU + xt.y * alpha;
        m2 = m2 * TAU + xt.z * alpha;
        m3 = m3 * TAU + xt.w * alpha;

        float4 s;
        s.x = (m0 - vth > 0.f) ? 1.f : 0.f;
        s.y = (m1 - vth > 0.f) ? 1.f : 0.f;
        s.z = (m2 - vth > 0.f) ? 1.f : 0.f;
        s.w = (m3 - vth > 0.f) ? 1.f : 0.f;

        // hard reset: mem = (1 - spike) * mem  (spike==1 -> mem = 0)
        m0 = (s.x > 0.f) ? 0.f : m0;
        m1 = (s.y > 0.f) ? 0.f : m1;
        m2 = (s.z > 0.f) ? 0.f : m2;
        m3 = (s.w > 0.f) ? 0.f : m3;

        *reinterpret_cast<float4*>(out + (size_t)t * (size_t)spatial + i4) = s;
    }
}

extern "C" void kernel_launch(void* const* d_in, const int* in_sizes, int n_in,
                              void* d_out, int out_size) {
    const float* x     = (const float*)d_in[0];
    const float* alpha = (const float*)d_in[1];
    const float* vth   = (const float*)d_in[2];
    float* out = (float*)d_out;

    const int total   = in_sizes[0];     // T * spatial
    const int spatial = total / 8;       // T = 8

    const int threads = 256;
    const int elems_per_thread = 4;
    const int blocks = (spatial + threads * elems_per_thread - 1) /
                       (threads * elems_per_thread);

    lif_spike_kernel<<<blocks, threads>>>(x, alpha, vth, out, spatial);
}

// round 2
// speedup vs baseline: 1.0449x; 1.0449x over previous
#include <cuda_runtime.h>

// LIF spike recurrence, T=8:
//   mem = mem*TAU + x[t]*alpha; spike = (mem - Vth) > 0; mem = (1-spike)*mem
// Each thread owns 4 spatial positions (float4). All 8 timestep loads are
// front-batched into registers (MLP=8 LDG.128), then the recurrence runs,
// then all 8 stores issue. Streaming cache hints (no reuse).

#define TAU 0.5f

__global__ void __launch_bounds__(256) lif_spike_kernel(
    const float* __restrict__ x,
    const float* __restrict__ alpha_p,
    const float* __restrict__ vth_p,
    float* __restrict__ out,
    int spatial /* elements per timestep */)
{
    const float alpha = __ldg(alpha_p);
    const float vth   = __ldg(vth_p);

    const int i4 = (blockIdx.x * blockDim.x + threadIdx.x) * 4;
    if (i4 >= spatial) return;

    // ── Front-batch all 8 timestep loads (8 independent LDG.128) ──
    float4 xt[8];
    #pragma unroll
    for (int t = 0; t < 8; t++) {
        xt[t] = __ldcs(reinterpret_cast<const float4*>(
            x + (size_t)t * (size_t)spatial + i4));
    }

    // ── Recurrence in registers ──
    float m0 = 0.f, m1 = 0.f, m2 = 0.f, m3 = 0.f;
    float4 s[8];
    #pragma unroll
    for (int t = 0; t < 8; t++) {
        m0 = m0 * TAU + xt[t].x * alpha;
        m1 = m1 * TAU + xt[t].y * alpha;
        m2 = m2 * TAU + xt[t].z * alpha;
        m3 = m3 * TAU + xt[t].w * alpha;

        s[t].x = (m0 > vth) ? 1.f : 0.f;
        s[t].y = (m1 > vth) ? 1.f : 0.f;
        s[t].z = (m2 > vth) ? 1.f : 0.f;
        s[t].w = (m3 > vth) ? 1.f : 0.f;

        // hard reset on spike
        m0 = (m0 > vth) ? 0.f : m0;
        m1 = (m1 > vth) ? 0.f : m1;
        m2 = (m2 > vth) ? 0.f : m2;
        m3 = (m3 > vth) ? 0.f : m3;
    }

    // ── Batched stores ──
    #pragma unroll
    for (int t = 0; t < 8; t++) {
        __stcs(reinterpret_cast<float4*>(
            out + (size_t)t * (size_t)spatial + i4), s[t]);
    }
}

extern "C" void kernel_launch(void* const* d_in, const int* in_sizes, int n_in,
                              void* d_out, int out_size) {
    const float* x     = (const float*)d_in[0];
    const float* alpha = (const float*)d_in[1];
    const float* vth   = (const float*)d_in[2];
    float* out = (float*)d_out;

    const int total   = in_sizes[0];     // T * spatial
    const int spatial = total / 8;       // T = 8

    const int threads = 256;
    const int elems_per_thread = 4;
    const int blocks = (spatial + threads * elems_per_thread - 1) /
                       (threads * elems_per_thread);

    lif_spike_kernel<<<blocks, threads>>>(x, alpha, vth, out, spatial);
}